// round 13
// baseline (speedup 1.0000x reference)
#include <cuda_runtime.h>
#include <cuda_fp16.h>

// SimpleGRU: B=2048, T=2048, H=32, scalar input.
// One warp = FOUR batches as two packed half2 streams ({A,B},{C,D}).
// Grid 512 single-warp blocks -> <=1 warp/SMSP: warp owns the fma pipe.
// Phase-interleaved: r/z chains of BOTH streams first (4-way interleave,
// depth 32, latency slack), 4 sigmoid MUFUs fire and retire under the
// n-chains, tails last. No syncwarp (convergent warp + parity buffer).
// H held in registers across phases (launch_bounds(32,1): no spill).

#define FULL_MASK 0xffffffffu

__device__ __forceinline__ __half2 htanh2(__half2 a) {
    unsigned int d, s = *reinterpret_cast<unsigned int*>(&a);
    asm("tanh.approx.f16x2 %0, %1;" : "=r"(d) : "r"(s));
    return *reinterpret_cast<__half2*>(&d);
}
__device__ __forceinline__ __half2 u2h(unsigned int u) {
    return *reinterpret_cast<const __half2*>(&u);
}
__device__ __forceinline__ unsigned int h2u(__half2 h) {
    return *reinterpret_cast<unsigned int*>(&h);
}

__global__ void __launch_bounds__(32, 1)
gru_kernel(const float* __restrict__ x,
           const float* __restrict__ w_ih,
           const float* __restrict__ w_hh,
           const float* __restrict__ b_ih,
           const float* __restrict__ b_hh,
           const float* __restrict__ head_w,
           const float* __restrict__ head_b,
           float* __restrict__ out,
           int B, int T)
{
    const int b0 = blockIdx.x * 4;          // four batch elements per warp
    const int i  = threadIdx.x;             // lane == hidden unit, H == 32

    // [parity][2*j + s]: s=0 -> {hA_j,hB_j}, s=1 -> {hC_j,hD_j}
    __shared__ __align__(16) unsigned int hsh[2][64];

    // Duplicated {w,w} W_hh rows for unit i; r,z prescaled by 0.5.
    __half2 wr[32], wz[32], wn[32];
    {
        const float* Wr = w_hh + (0  + i) * 32;
        const float* Wz = w_hh + (32 + i) * 32;
        const float* Wn = w_hh + (64 + i) * 32;
        #pragma unroll
        for (int j = 0; j < 32; j++) {
            wr[j] = __float2half2_rn(Wr[j] * 0.5f);
            wz[j] = __float2half2_rn(Wz[j] * 0.5f);
            wn[j] = __float2half2_rn(Wn[j]);
        }
    }

    const __half2 wir2 = __float2half2_rn(w_ih[i]      * 0.5f);
    const __half2 cr2  = __float2half2_rn((b_ih[i]      + b_hh[i])      * 0.5f);
    const __half2 wiz2 = __float2half2_rn(w_ih[32 + i] * 0.5f);
    const __half2 cz2  = __float2half2_rn((b_ih[32 + i] + b_hh[32 + i]) * 0.5f);
    const __half2 win2 = __float2half2_rn(w_ih[64 + i]);
    const __half2 cnx2 = __float2half2_rn(b_ih[64 + i]);
    const __half2 cnh2 = __float2half2_rn(b_hh[64 + i]);
    const __half2 hlf2 = __float2half2_rn(0.5f);
    const __half2 zero = __float2half2_rn(0.0f);

    __half2 h2a = zero;                     // {hA_i, hB_i}
    __half2 h2b = zero;                     // {hC_i, hD_i}
    const float* xA = x + (long long)b0 * T;
    const float* xB = xA + T;
    const float* xC = xB + T;
    const float* xD = xC + T;

    for (int t0 = 0; t0 < T; t0 += 32) {
        unsigned int xpa = h2u(__floats2half2_rn(xA[t0 + i], xB[t0 + i]));
        unsigned int xpb = h2u(__floats2half2_rn(xC[t0 + i], xD[t0 + i]));
        #pragma unroll 2
        for (int kk = 0; kk < 16; kk++) {
            #pragma unroll
            for (int p = 0; p < 2; p++) {   // manual parity unroll, static addrs
                const int k = 2 * kk + p;
                __half2 xta = u2h(__shfl_sync(FULL_MASK, xpa, k));
                __half2 xtb = u2h(__shfl_sync(FULL_MASK, xpb, k));

                // One STS.64: both streams' packed h for this unit.
                *reinterpret_cast<uint2*>(&hsh[p][2 * i]) =
                    make_uint2(h2u(h2a), h2u(h2b));
                asm volatile("" ::: "memory");  // compiler fence only

                // 16x LDS.128: all 64 packed pairs, kept in registers
                // for both phases.
                unsigned int HA[32], HB[32];
                {
                    const uint4* hp = (const uint4*)&hsh[p][0];
                    #pragma unroll
                    for (int jj = 0; jj < 16; jj++) {
                        uint4 q = hp[jj];   // {a_{2jj}, b_{2jj}, a_{2jj+1}, b_{2jj+1}}
                        HA[2*jj]   = q.x;  HB[2*jj]   = q.y;
                        HA[2*jj+1] = q.z;  HB[2*jj+1] = q.w;
                    }
                }

                // Phase 1: r,z for BOTH streams, single depth-32 chains,
                // 4-way interleaved (8-cyc chain spacing >> lat 4).
                __half2 rA = __hfma2(xta, wir2, cr2);
                __half2 zA = __hfma2(xta, wiz2, cz2);
                __half2 rB = __hfma2(xtb, wir2, cr2);
                __half2 zB = __hfma2(xtb, wiz2, cz2);
                #pragma unroll
                for (int j = 0; j < 32; j++) {
                    __half2 ga = u2h(HA[j]), gb = u2h(HB[j]);
                    rA = __hfma2(wr[j], ga, rA);
                    zA = __hfma2(wz[j], ga, zA);
                    rB = __hfma2(wr[j], gb, rB);
                    zB = __hfma2(wz[j], gb, zB);
                }
                // Fire all 4 sigmoid MUFUs; they retire under the n-chains.
                __half2 trA = htanh2(rA), tzA = htanh2(zA);
                __half2 trB = htanh2(rB), tzB = htanh2(zB);

                // Phase 2: n-chains, 2 per stream (depth 16).
                __half2 nA0 = cnh2, nA1 = zero, nB0 = cnh2, nB1 = zero;
                #pragma unroll
                for (int j = 0; j < 32; j += 2) {
                    nA0 = __hfma2(wn[j],     u2h(HA[j]),     nA0);
                    nA1 = __hfma2(wn[j + 1], u2h(HA[j + 1]), nA1);
                    nB0 = __hfma2(wn[j],     u2h(HB[j]),     nB0);
                    nB1 = __hfma2(wn[j + 1], u2h(HB[j + 1]), nB1);
                }

                // Stream 1 tail.
                {
                    __half2 rg = __hfma2(trA, hlf2, hlf2);
                    __half2 zg = __hfma2(tzA, hlf2, hlf2);
                    __half2 hn2 = __hadd2(nA0, nA1);
                    __half2 narg = __hfma2(rg, hn2, __hfma2(xta, win2, cnx2));
                    __half2 ng = htanh2(narg);
                    h2a = __hfma2(zg, __hsub2(h2a, ng), ng);
                }
                // Stream 2 tail.
                {
                    __half2 rg = __hfma2(trB, hlf2, hlf2);
                    __half2 zg = __hfma2(tzB, hlf2, hlf2);
                    __half2 hn2 = __hadd2(nB0, nB1);
                    __half2 narg = __hfma2(rg, hn2, __hfma2(xtb, win2, cnx2));
                    __half2 ng = htanh2(narg);
                    h2b = __hfma2(zg, __hsub2(h2b, ng), ng);
                }
            }
        }
    }

    // Head: out[b][o] = sum_i h_i * head_w[o][i] + head_b[o]  (fp32)
    float2 fa = __half22float2(h2a);
    float2 fb = __half22float2(h2b);
    float w0 = head_w[i], w1 = head_w[32 + i];
    float p[8] = { fa.x * w0, fa.x * w1, fa.y * w0, fa.y * w1,
                   fb.x * w0, fb.x * w1, fb.y * w0, fb.y * w1 };
    #pragma unroll
    for (int m = 16; m > 0; m >>= 1) {
        #pragma unroll
        for (int q = 0; q < 8; q++)
            p[q] += __shfl_xor_sync(FULL_MASK, p[q], m);
    }
    if (i == 0) {
        #pragma unroll
        for (int q = 0; q < 8; q++)
            out[2 * b0 + q] = p[q] + head_b[q & 1];
    }
}

extern "C" void kernel_launch(void* const* d_in, const int* in_sizes, int n_in,
                              void* d_out, int out_size) {
    const float* x      = (const float*)d_in[0];
    const float* w_ih   = (const float*)d_in[1];
    const float* w_hh   = (const float*)d_in[2];
    const float* b_ih   = (const float*)d_in[3];
    const float* b_hh   = (const float*)d_in[4];
    const float* head_w = (const float*)d_in[5];
    const float* head_b = (const float*)d_in[6];
    float* out = (float*)d_out;

    const int B = out_size / 2;           // 2048
    const int T = in_sizes[0] / B;        // 2048

    gru_kernel<<<B / 4, 32>>>(x, w_ih, w_hh, b_ih, b_hh, head_w, head_b, out, B, T);
}

// round 14
// speedup vs baseline: 1.0343x; 1.0343x over previous
#include <cuda_runtime.h>
#include <cuda_fp16.h>

// SimpleGRU: B=2048, T=2048, H=32, scalar input.
// One warp = two batch elements; lane i = hidden unit i of both.
// Interleaved-batch packing: state h2 = {hA_i, hB_i} half2; weights {w,w}.
// R14 = R12 skeleton + software-pipelined x prefetch: the next 32-step
// chunk's x LDGs issue a full chunk early (~15k cyc of slack), removing
// the cold-load stall that sat on the critical path at every chunk start.
// Phased math: r,z single depth-32 chains -> sigmoid MUFUs fire -> n-chains
// (2x depth 16) retire the MUFUs -> short tail. No syncwarp (convergent
// warp, parity double-buffer). Sigmoid via tanh.approx.f16x2.

#define FULL_MASK 0xffffffffu

__device__ __forceinline__ __half2 htanh2(__half2 a) {
    unsigned int d, s = *reinterpret_cast<unsigned int*>(&a);
    asm("tanh.approx.f16x2 %0, %1;" : "=r"(d) : "r"(s));
    return *reinterpret_cast<__half2*>(&d);
}
__device__ __forceinline__ __half2 u2h(unsigned int u) {
    return *reinterpret_cast<const __half2*>(&u);
}
__device__ __forceinline__ unsigned int h2u(__half2 h) {
    return *reinterpret_cast<unsigned int*>(&h);
}

__global__ void __launch_bounds__(32, 1)
gru_kernel(const float* __restrict__ x,
           const float* __restrict__ w_ih,
           const float* __restrict__ w_hh,
           const float* __restrict__ b_ih,
           const float* __restrict__ b_hh,
           const float* __restrict__ head_w,
           const float* __restrict__ head_b,
           float* __restrict__ out,
           int B, int T)
{
    const int b0 = blockIdx.x * 2;          // two batch elements per warp
    const int i  = threadIdx.x;             // lane == hidden unit, H == 32

    // [parity][unit j] -> packed {hA_j, hB_j}
    __shared__ __align__(16) unsigned int hsh[2][32];

    // Duplicated {w,w} W_hh rows for unit i; r,z prescaled by 0.5.
    __half2 wr[32], wz[32], wn[32];
    {
        const float* Wr = w_hh + (0  + i) * 32;
        const float* Wz = w_hh + (32 + i) * 32;
        const float* Wn = w_hh + (64 + i) * 32;
        #pragma unroll
        for (int j = 0; j < 32; j++) {
            wr[j] = __float2half2_rn(Wr[j] * 0.5f);
            wz[j] = __float2half2_rn(Wz[j] * 0.5f);
            wn[j] = __float2half2_rn(Wn[j]);
        }
    }

    const __half2 wir2 = __float2half2_rn(w_ih[i]      * 0.5f);
    const __half2 cr2  = __float2half2_rn((b_ih[i]      + b_hh[i])      * 0.5f);
    const __half2 wiz2 = __float2half2_rn(w_ih[32 + i] * 0.5f);
    const __half2 cz2  = __float2half2_rn((b_ih[32 + i] + b_hh[32 + i]) * 0.5f);
    const __half2 win2 = __float2half2_rn(w_ih[64 + i]);
    const __half2 cnx2 = __float2half2_rn(b_ih[64 + i]);
    const __half2 cnh2 = __float2half2_rn(b_hh[64 + i]);
    const __half2 hlf2 = __float2half2_rn(0.5f);
    const __half2 zero = __float2half2_rn(0.0f);

    __half2 h2 = zero;                      // packed state {hA_i, hB_i}
    const float* xA = x + (long long)b0 * T;
    const float* xB = xA + T;

    // Prime the x pipeline: chunk 0 loaded up front.
    float xa_cur = xA[i];
    float xb_cur = xB[i];

    for (int t0 = 0; t0 < T; t0 += 32) {
        // Prefetch NEXT chunk's x now; consumed 32 steps (~15k cyc) later.
        const int tn = (t0 + 32 < T) ? (t0 + 32) : t0;   // clamp: safe addr
        float xa_nxt = xA[tn + i];
        float xb_nxt = xB[tn + i];

        unsigned int xp = h2u(__floats2half2_rn(xa_cur, xb_cur));

        #pragma unroll 2
        for (int kk = 0; kk < 16; kk++) {
            #pragma unroll
            for (int p = 0; p < 2; p++) {   // manual parity unroll, static addrs
                const int k = 2 * kk + p;
                __half2 xt2 = u2h(__shfl_sync(FULL_MASK, xp, k));

                hsh[p][i] = h2u(h2);            // one raw STS.32
                asm volatile("" ::: "memory");  // compiler fence only

                // 8x LDS.128 broadcast: all 32 packed h pairs.
                const uint4* hp = (const uint4*)&hsh[p][0];
                uint4 q0 = hp[0], q1 = hp[1], q2 = hp[2], q3 = hp[3];
                uint4 q4 = hp[4], q5 = hp[5], q6 = hp[6], q7 = hp[7];
                unsigned int H[32] = {q0.x,q0.y,q0.z,q0.w, q1.x,q1.y,q1.z,q1.w,
                                      q2.x,q2.y,q2.z,q2.w, q3.x,q3.y,q3.z,q3.w,
                                      q4.x,q4.y,q4.z,q4.w, q5.x,q5.y,q5.z,q5.w,
                                      q6.x,q6.y,q6.z,q6.w, q7.x,q7.y,q7.z,q7.w};

                // Phase 1: r and z as single depth-32 chains, 2-way
                // interleaved. x-side folded into inits.
                __half2 r0 = __hfma2(xt2, wir2, cr2);
                __half2 z0 = __hfma2(xt2, wiz2, cz2);
                #pragma unroll
                for (int j = 0; j < 32; j++) {
                    __half2 g = u2h(H[j]);
                    r0 = __hfma2(wr[j], g, r0);
                    z0 = __hfma2(wz[j], g, z0);
                }
                // Fire both sigmoid MUFUs; they retire under the n-chain.
                __half2 tr = htanh2(r0);
                __half2 tz = htanh2(z0);

                // Phase 2: n as 2 chains depth 16 (h-side bias in chain0).
                __half2 n0 = cnh2, n1 = zero;
                #pragma unroll
                for (int j = 0; j < 32; j += 2) {
                    n0 = __hfma2(wn[j],     u2h(H[j]),     n0);
                    n1 = __hfma2(wn[j + 1], u2h(H[j + 1]), n1);
                }
                __half2 hn2 = __hadd2(n0, n1);

                // Tail: short exposed chain only.
                __half2 rg = __hfma2(tr, hlf2, hlf2);            // sigmoid
                __half2 zg = __hfma2(tz, hlf2, hlf2);
                __half2 narg = __hfma2(rg, hn2, __hfma2(xt2, win2, cnx2));
                __half2 ng = htanh2(narg);
                h2 = __hfma2(zg, __hsub2(h2, ng), ng);  // (1-z)*n + z*h
            }
        }

        xa_cur = xa_nxt;
        xb_cur = xb_nxt;
    }

    // Head: out[b][o] = sum_i h_i * head_w[o][i] + head_b[o]  (fp32)
    float2 hf = __half22float2(h2);
    float ha = hf.x, hb = hf.y;
    float p0a = ha * head_w[i], p1a = ha * head_w[32 + i];
    float p0b = hb * head_w[i], p1b = hb * head_w[32 + i];
    #pragma unroll
    for (int m = 16; m > 0; m >>= 1) {
        p0a += __shfl_xor_sync(FULL_MASK, p0a, m);
        p1a += __shfl_xor_sync(FULL_MASK, p1a, m);
        p0b += __shfl_xor_sync(FULL_MASK, p0b, m);
        p1b += __shfl_xor_sync(FULL_MASK, p1b, m);
    }
    if (i == 0) {
        out[2 * b0]     = p0a + head_b[0];
        out[2 * b0 + 1] = p1a + head_b[1];
        out[2 * b0 + 2] = p0b + head_b[0];
        out[2 * b0 + 3] = p1b + head_b[1];
    }
}

extern "C" void kernel_launch(void* const* d_in, const int* in_sizes, int n_in,
                              void* d_out, int out_size) {
    const float* x      = (const float*)d_in[0];
    const float* w_ih   = (const float*)d_in[1];
    const float* w_hh   = (const float*)d_in[2];
    const float* b_ih   = (const float*)d_in[3];
    const float* b_hh   = (const float*)d_in[4];
    const float* head_w = (const float*)d_in[5];
    const float* head_b = (const float*)d_in[6];
    float* out = (float*)d_out;

    const int B = out_size / 2;           // 2048
    const int T = in_sizes[0] / B;        // 2048

    gru_kernel<<<B / 2, 32>>>(x, w_ih, w_hh, b_ih, b_hh, head_w, head_b, out, B, T);
}

// round 15
// speedup vs baseline: 1.4603x; 1.4119x over previous
#include <cuda_runtime.h>
#include <cuda_fp16.h>

// SimpleGRU: B=2048, T=2048, H=32, scalar input.
// R15: warp-level tensor cores. One warp = EIGHT batch elements.
// Per step: preacts = mma.m16n8k16 (A = W_hh stationary in fragments,
// B = h vector, n=8 batch columns, fp32 accumulate, biases folded into C).
// 12 HMMA/step replace the scalar matvec. h -> B-fragment rebuild via
// 8 shfl + 4 prmt (no smem for h). Gate tail local per thread (D layout
// puts all 3 gates of a unit on the same thread). x via smem chunk buffer.
// Thread map: gid = tid>>2 (0..7), tig = tid&3; thread holds units
// {gid, gid+8, gid+16, gid+24} x batches {2tig, 2tig+1}.

#define FULL_MASK 0xffffffffu

__device__ __forceinline__ __half2 htanh2(__half2 a) {
    unsigned int d, s = *reinterpret_cast<unsigned int*>(&a);
    asm("tanh.approx.f16x2 %0, %1;" : "=r"(d) : "r"(s));
    return *reinterpret_cast<__half2*>(&d);
}
__device__ __forceinline__ __half2 u2h(unsigned int u) {
    return *reinterpret_cast<const __half2*>(&u);
}
__device__ __forceinline__ unsigned int h2u(__half2 h) {
    return *reinterpret_cast<unsigned int*>(&h);
}
__device__ __forceinline__ unsigned int packh2(float lo, float hi) {
    return h2u(__floats2half2_rn(lo, hi));
}
__device__ __forceinline__ void mma16816(float* d,
                                         const unsigned* a,
                                         unsigned b0, unsigned b1,
                                         const float* c) {
    asm volatile(
        "mma.sync.aligned.m16n8k16.row.col.f32.f16.f16.f32 "
        "{%0,%1,%2,%3}, {%4,%5,%6,%7}, {%8,%9}, {%10,%11,%12,%13};"
        : "=f"(d[0]), "=f"(d[1]), "=f"(d[2]), "=f"(d[3])
        : "r"(a[0]), "r"(a[1]), "r"(a[2]), "r"(a[3]),
          "r"(b0), "r"(b1),
          "f"(c[0]), "f"(c[1]), "f"(c[2]), "f"(c[3]));
}
__device__ __forceinline__ unsigned int prmt(unsigned int a, unsigned int b,
                                             unsigned int c) {
    unsigned int d;
    asm("prmt.b32 %0, %1, %2, %3;" : "=r"(d) : "r"(a), "r"(b), "r"(c));
    return d;
}

__global__ void __launch_bounds__(32, 1)
gru_kernel(const float* __restrict__ x,
           const float* __restrict__ w_ih,
           const float* __restrict__ w_hh,
           const float* __restrict__ b_ih,
           const float* __restrict__ b_hh,
           const float* __restrict__ head_w,
           const float* __restrict__ head_b,
           float* __restrict__ out,
           int B, int T)
{
    const int b0  = blockIdx.x * 8;         // eight batches per warp
    const int tid = threadIdx.x;
    const int gid = tid >> 2;               // 0..7
    const int tig = tid & 3;                // 0..3

    // x chunk buffer: [chunk parity][t 0..31][batch 0..7] halves
    __shared__ __align__(16) __half xbuf[2][32][8];

    // ---- A fragments: W_hh stationary (r,z scaled 0.5 for sigmoid-via-tanh)
    // tile t: rows 16t..16t+15 of the 96-row W (gate = t/2); k-tile kt: cols 16kt..
    unsigned int a[6][2][4];
    #pragma unroll
    for (int t = 0; t < 6; t++) {
        const float s = (t < 4) ? 0.5f : 1.0f;
        #pragma unroll
        for (int kt = 0; kt < 2; kt++) {
            const int r0 = 16 * t + gid, r1 = r0 + 8;
            const int c  = 16 * kt + 2 * tig;
            a[t][kt][0] = packh2(w_hh[r0 * 32 + c] * s,     w_hh[r0 * 32 + c + 1] * s);
            a[t][kt][1] = packh2(w_hh[r1 * 32 + c] * s,     w_hh[r1 * 32 + c + 1] * s);
            a[t][kt][2] = packh2(w_hh[r0 * 32 + c + 8] * s, w_hh[r0 * 32 + c + 9] * s);
            a[t][kt][3] = packh2(w_hh[r1 * 32 + c + 8] * s, w_hh[r1 * 32 + c + 9] * s);
        }
    }

    // ---- C initializers: bias per row (same for all batch cols).
    // r,z rows: 0.5*(b_ih+b_hh); n rows: b_hh only (h-side bias).
    float cinit[6][4];
    #pragma unroll
    for (int t = 0; t < 6; t++) {
        const int r0 = 16 * t + gid, r1 = r0 + 8;
        float v0, v1;
        if (t < 4) { v0 = 0.5f * (b_ih[r0] + b_hh[r0]);
                     v1 = 0.5f * (b_ih[r1] + b_hh[r1]); }
        else       { v0 = b_hh[r0]; v1 = b_hh[r1]; }
        cinit[t][0] = v0; cinit[t][1] = v0;
        cinit[t][2] = v1; cinit[t][3] = v1;
    }

    // ---- tail constants per owned unit u = gid + 8j
    __half2 wir2[4], wiz2[4], win2[4], cnx2[4];
    #pragma unroll
    for (int j = 0; j < 4; j++) {
        const int u = gid + 8 * j;
        wir2[j] = __float2half2_rn(w_ih[u]      * 0.5f);
        wiz2[j] = __float2half2_rn(w_ih[32 + u] * 0.5f);
        win2[j] = __float2half2_rn(w_ih[64 + u]);
        cnx2[j] = __float2half2_rn(b_ih[64 + u]);
    }
    const __half2 hlf2 = __float2half2_rn(0.5f);

    // ---- B-fragment rebuild constants
    const int srcA = 8 * tig + (gid >> 1);          // lane holding h[2tig+..][gid]
    const int srcB = srcA + 4;                      // lane holding h[2tig+1+..][gid]
    const unsigned int pctl = (gid & 1) ? 0x7632u : 0x5410u;  // half select

    // ---- state: h[u][b] for u = gid+8j, b = {2tig, 2tig+1}
    __half2 h2[4];
    #pragma unroll
    for (int j = 0; j < 4; j++) h2[j] = __float2half2_rn(0.0f);

    // ---- x pipeline: lane l covers t-offset l, all 8 batches
    const float* xb = x + (long long)b0 * T;
    float xv[8];
    #pragma unroll
    for (int b = 0; b < 8; b++) xv[b] = xb[b * T + tid];

    for (int t0 = 0; t0 < T; t0 += 32) {
        const int cp = (t0 >> 5) & 1;
        // store current chunk's x (loaded last iteration) as halves
        {
            uint4 pk;
            pk.x = packh2(xv[0], xv[1]);
            pk.y = packh2(xv[2], xv[3]);
            pk.z = packh2(xv[4], xv[5]);
            pk.w = packh2(xv[6], xv[7]);
            *reinterpret_cast<uint4*>(&xbuf[cp][tid][0]) = pk;
        }
        asm volatile("" ::: "memory");
        // prefetch next chunk's x (consumed a whole chunk later)
        {
            const int tn = (t0 + 32 < T) ? (t0 + 32) : t0;
            #pragma unroll
            for (int b = 0; b < 8; b++) xv[b] = xb[b * T + tn + tid];
        }

        for (int k = 0; k < 32; k++) {
            // x for this step, batches {2tig, 2tig+1}
            __half2 xt2 = *reinterpret_cast<const __half2*>(&xbuf[cp][k][2 * tig]);

            // ---- rebuild B fragments from h2 via shuffles ----
            unsigned int hu0 = h2u(h2[0]), hu1 = h2u(h2[1]);
            unsigned int hu2 = h2u(h2[2]), hu3 = h2u(h2[3]);
            unsigned int b00 = prmt(__shfl_sync(FULL_MASK, hu0, srcA),
                                    __shfl_sync(FULL_MASK, hu0, srcB), pctl);
            unsigned int b01 = prmt(__shfl_sync(FULL_MASK, hu1, srcA),
                                    __shfl_sync(FULL_MASK, hu1, srcB), pctl);
            unsigned int b10 = prmt(__shfl_sync(FULL_MASK, hu2, srcA),
                                    __shfl_sync(FULL_MASK, hu2, srcB), pctl);
            unsigned int b11 = prmt(__shfl_sync(FULL_MASK, hu3, srcA),
                                    __shfl_sync(FULL_MASK, hu3, srcB), pctl);

            // ---- 12 HMMA: 6 m-tiles x 2 k-tiles, fp32 accumulate ----
            float d[6][4];
            #pragma unroll
            for (int t = 0; t < 6; t++)
                mma16816(d[t], a[t][0], b00, b01, cinit[t]);
            #pragma unroll
            for (int t = 0; t < 6; t++)
                mma16816(d[t], a[t][1], b10, b11, d[t]);

            // ---- gate tail: 4 owned units, batches packed {2tig, 2tig+1} ----
            #pragma unroll
            for (int j = 0; j < 4; j++) {
                const int ts  = (j >= 2) ? 1 : 0;     // tile select within gate
                const int off = (j & 1) ? 2 : 0;      // d-register pair
                __half2 hr2 = __floats2half2_rn(d[ts][off],     d[ts][off + 1]);
                __half2 hz2 = __floats2half2_rn(d[2 + ts][off], d[2 + ts][off + 1]);
                __half2 hn2 = __floats2half2_rn(d[4 + ts][off], d[4 + ts][off + 1]);

                __half2 pre_r = __hfma2(xt2, wir2[j], hr2);  // 0.5*preact (bias in C)
                __half2 pre_z = __hfma2(xt2, wiz2[j], hz2);
                __half2 rg = __hfma2(htanh2(pre_r), hlf2, hlf2);   // sigmoid
                __half2 zg = __hfma2(htanh2(pre_z), hlf2, hlf2);
                __half2 xn2 = __hfma2(xt2, win2[j], cnx2[j]);
                __half2 ng = htanh2(__hfma2(rg, hn2, xn2));
                h2[j] = __hfma2(zg, __hsub2(h2[j], ng), ng);
            }
        }
    }

    // ---- head: out[b][o] = sum_u h[u][b] * head_w[o][u] + head_b[o] ----
    float pA0 = 0.f, pA1 = 0.f, pB0 = 0.f, pB1 = 0.f;  // A=batch 2tig, B=2tig+1
    #pragma unroll
    for (int j = 0; j < 4; j++) {
        const int u = gid + 8 * j;
        float2 hf = __half22float2(h2[j]);
        float w0 = head_w[u], w1 = head_w[32 + u];
        pA0 += hf.x * w0;  pA1 += hf.x * w1;
        pB0 += hf.y * w0;  pB1 += hf.y * w1;
    }
    // reduce across gid (lanes with same tig): xor masks 4, 8, 16
    #pragma unroll
    for (int m = 4; m <= 16; m <<= 1) {
        pA0 += __shfl_xor_sync(FULL_MASK, pA0, m);
        pA1 += __shfl_xor_sync(FULL_MASK, pA1, m);
        pB0 += __shfl_xor_sync(FULL_MASK, pB0, m);
        pB1 += __shfl_xor_sync(FULL_MASK, pB1, m);
    }
    if (gid == 0) {                          // tid 0..3 (= tig)
        const int ba = b0 + 2 * tig;
        out[ba * 2]           = pA0 + head_b[0];
        out[ba * 2 + 1]       = pA1 + head_b[1];
        out[(ba + 1) * 2]     = pB0 + head_b[0];
        out[(ba + 1) * 2 + 1] = pB1 + head_b[1];
    }
}

extern "C" void kernel_launch(void* const* d_in, const int* in_sizes, int n_in,
                              void* d_out, int out_size) {
    const float* x      = (const float*)d_in[0];
    const float* w_ih   = (const float*)d_in[1];
    const float* w_hh   = (const float*)d_in[2];
    const float* b_ih   = (const float*)d_in[3];
    const float* b_hh   = (const float*)d_in[4];
    const float* head_w = (const float*)d_in[5];
    const float* head_b = (const float*)d_in[6];
    float* out = (float*)d_out;

    const int B = out_size / 2;           // 2048
    const int T = in_sizes[0] / B;        // 2048

    gru_kernel<<<B / 8, 32>>>(x, w_ih, w_hh, b_ih, b_hh, head_w, head_b, out, B, T);
}